// round 14
// baseline (speedup 1.0000x reference)
#include <cuda_runtime.h>

// GaussianBlurDM, round 13: break FFMA register-bank parity coupling.
//
// out[b] = reflect-conv(reflect-conv(x[b], K_t, axis=H), K_t, axis=W),
// K_t = t-fold self-convolution of the 11-tap Gaussian (exact DCT-I identity),
// truncated at tail mass 2.5e-4 (exact odd tap count).
//
// R12 finding: float2 accumulators force acc.x/ring.x both into EVEN banks and
// acc.y/ring.y both into ODD banks -> every FFMA reads 2 same-parity registers
// -> rt=2 despite the rt=1 immediate form. Fix: accumulators are 16
// independent scalars (accx[8]/accy[8]) so ptxas can pair each FFMA's two
// register reads across banks -> rt=1. Rings stay float2 (64-bit loads).

#define BATCH 64
#define CHAN 3
#define IMG 256
#define NT 19
#define KW 80              // weight array length
#define SVSTRIDE 18        // floats per sv column (16 rows + 2 pad)

// ---------------------------------------------------------------------------
// Compile-time weight table.
// ---------------------------------------------------------------------------
struct KTab {
    float w[NT][KW];
    int nd[NT];
    int rl[NT];
};

constexpr KTab make_ktab() {
    KTab T{};
    // q = e^{-1/8} by Taylor (full double precision)
    double q = 1.0;
    {
        double term = 1.0;
        for (int i = 1; i < 26; ++i) { term *= (-0.125) / (double)i; q += term; }
    }
    // base pdf[x] = q^(x^2), x = -5..5 ; f32-rounded normalized (matches _k1d)
    double base[11] = {};
    double sum = 0.0;
    for (int x = -5; x <= 5; ++x) {
        double p = 1.0;
        for (int i = 0; i < x * x; ++i) p *= q;
        base[x + 5] = p;
        sum += p;
    }
    for (int i = 0; i < 11; ++i) base[i] = (double)((float)(base[i] / sum));

    double f[220] = {};
    for (int i = 0; i < 11; ++i) f[i] = base[i];
    int hw = 5;
    for (int tt = 1; tt <= NT; ++tt) {
        double acc = 0.0;
        int r = 0;
        for (int a = hw; a >= 1; --a) {
            acc += f[hw + a];
            if (2.0 * acc > 2.5e-4) { r = a; break; }
        }
        T.nd[tt - 1] = 2 * r + 1;
        T.rl[tt - 1] = r;
        for (int j = 0; j <= 2 * r; ++j) T.w[tt - 1][j] = (float)f[hw + j - r];
        if (tt < NT) {                       // f = f (*) base
            double g[220] = {};
            int L = 2 * hw + 1;
            for (int n = 0; n < L; ++n) {
                double fn = f[n];
                for (int k = 0; k < 11; ++k) g[n + k] += fn * base[k];
            }
            for (int i = 0; i < 220; ++i) f[i] = g[i];
            hw += 5;
        }
    }
    return T;
}
constexpr KTab KT = make_ktab();

struct BlurParams { float K[NT][KW]; };   // runtime copy for boundary paths

__device__ __forceinline__ int reflect256(int v) {
    v = abs(v);
    return (v > 255) ? (510 - v) : v;
}

// ---------------------------------------------------------------------------
// Template-recursive unrolled tap loops: FFMA with immediate weights,
// scalar accumulators (bank-parity free).
// ---------------------------------------------------------------------------
template<int TI, int J>
struct VTap {
    static __device__ __forceinline__ void run(
        float (&ax)[8], float (&ay)[8], float2 (&ring)[8],
        const float2* __restrict__ p)
    {
        constexpr float W = KT.w[TI][J];
        #pragma unroll
        for (int k = 0; k < 8; ++k) {
            float2 r = ring[(J + k) & 7];
            ax[k] = fmaf(r.x, W, ax[k]);
            ay[k] = fmaf(r.y, W, ay[k]);
        }
        if constexpr (J + 8 < KT.nd[TI] + 7)
            ring[J & 7] = __ldg(p + ((J + 8) << 7));     // row stride 128 f2
        if constexpr (J + 1 < KT.nd[TI])
            VTap<TI, J + 1>::run(ax, ay, ring, p);
    }
};

template<int TI, int J>
struct HTap {
    static __device__ __forceinline__ void run(
        float (&ax)[8], float (&ay)[8], float2 (&ring)[8],
        const float2* __restrict__ p)
    {
        constexpr float W = KT.w[TI][J];
        #pragma unroll
        for (int k = 0; k < 8; ++k) {
            float2 r = ring[(J + k) & 7];
            ax[k] = fmaf(r.x, W, ax[k]);
            ay[k] = fmaf(r.y, W, ay[k]);
        }
        if constexpr (J + 8 < KT.nd[TI] + 7)
            ring[J & 7] = p[(J + 8) * (SVSTRIDE / 2)];   // smem col stride
        if constexpr (J + 1 < KT.nd[TI])
            HTap<TI, J + 1>::run(ax, ay, ring, p);
    }
};

// ---------------------------------------------------------------------------
// Shared epilogues.
// ---------------------------------------------------------------------------
__device__ __forceinline__ void store_sv(float* sv, int cp_, int half,
                                         const float (&ax)[8],
                                         const float (&ay)[8])
{
    const int c0 = cp_ << 1;
    float* q0 = sv + c0 * SVSTRIDE + (half << 3);
    float* q1 = sv + (c0 + 1) * SVSTRIDE + (half << 3);
    #pragma unroll
    for (int q = 0; q < 4; ++q) {
        *(float2*)(q0 + 2 * q) = make_float2(ax[2 * q], ax[2 * q + 1]);
        *(float2*)(q1 + 2 * q) = make_float2(ay[2 * q], ay[2 * q + 1]);
    }
}

__device__ __forceinline__ void store_out(float* gout, int m0, int rp, int cg,
                                          const float (&ax)[8],
                                          const float (&ay)[8])
{
    float4* d0 = (float4*)(gout + (m0 + 2 * rp) * IMG + (cg << 3));
    float4* d1 = (float4*)(gout + (m0 + 2 * rp + 1) * IMG + (cg << 3));
    d0[0] = make_float4(ax[0], ax[1], ax[2], ax[3]);
    d0[1] = make_float4(ax[4], ax[5], ax[6], ax[7]);
    d1[0] = make_float4(ay[0], ay[1], ay[2], ay[3]);
    d1[1] = make_float4(ay[4], ay[5], ay[6], ay[7]);
}

// ---------------------------------------------------------------------------
// Boundary paths (runtime weights; one copy each).
// ---------------------------------------------------------------------------
__device__ __noinline__ void v_boundary(
    const float2* __restrict__ scol, float* __restrict__ sv,
    int cp_, int half, int vb, const float* __restrict__ Kf, int ndp)
{
    float ax[8] = {}, ay[8] = {};
    float2 ring[8];
    #pragma unroll
    for (int m = 0; m < 8; ++m)
        ring[m] = __ldg(scol + (reflect256(vb + m) << 7));
    #pragma unroll 1
    for (int jj = 0; jj < ndp; jj += 8) {
        #pragma unroll
        for (int u = 0; u < 8; ++u) {
            float W = Kf[jj + u];
            #pragma unroll
            for (int k = 0; k < 8; ++k) {
                float2 r = ring[(u + k) & 7];
                ax[k] = fmaf(r.x, W, ax[k]);
                ay[k] = fmaf(r.y, W, ay[k]);
            }
            ring[u] = __ldg(scol + (reflect256(vb + jj + u + 8) << 7));
        }
    }
    store_sv(sv, cp_, half, ax, ay);
}

__device__ __noinline__ void h_boundary(
    const float2* __restrict__ sb, float* __restrict__ gout,
    int rp, int cg, int qb, const float* __restrict__ Kf, int ndp, int m0)
{
    float ax[8] = {}, ay[8] = {};
    float2 ring[8];
    #pragma unroll
    for (int m = 0; m < 8; ++m)
        ring[m] = sb[reflect256(qb + m) * (SVSTRIDE / 2)];
    #pragma unroll 1
    for (int jj = 0; jj < ndp; jj += 8) {
        #pragma unroll
        for (int u = 0; u < 8; ++u) {
            float W = Kf[jj + u];
            #pragma unroll
            for (int k = 0; k < 8; ++k) {
                float2 r = ring[(u + k) & 7];
                ax[k] = fmaf(r.x, W, ax[k]);
                ay[k] = fmaf(r.y, W, ay[k]);
            }
            ring[u] = sb[reflect256(qb + jj + u + 8) * (SVSTRIDE / 2)];
        }
    }
    store_out(gout, m0, rp, cg, ax, ay);
}

// ---------------------------------------------------------------------------
// Per-t tile body: V pass (global -> sv transposed), H pass (sv -> out).
// ---------------------------------------------------------------------------
template<int TI>
__device__ __forceinline__ void tile_body(
    const float* __restrict__ img, float* __restrict__ gout, float* sv,
    int tid, int m0, const float* __restrict__ KfT)
{
    constexpr int ND = KT.nd[TI];
    constexpr int RL = KT.rl[TI];
    constexpr int NDP = (ND + 7) & ~7;

    // ---- V phase: thread = column pair x 8 rows ----
    {
        const int cp_ = tid & 127;
        const int half = tid >> 7;
        const float2* scol = (const float2*)img + cp_;
        const int vb = m0 + (half << 3) - RL;
        if (vb >= 0 && vb + ND + 7 <= 255) {
            float ax[8] = {}, ay[8] = {};
            float2 ring[8];
            const float2* p = scol + (vb << 7);
            #pragma unroll
            for (int m = 0; m < 8; ++m) ring[m] = __ldg(p + (m << 7));
            VTap<TI, 0>::run(ax, ay, ring, p);
            store_sv(sv, cp_, half, ax, ay);
        } else {
            v_boundary(scol, sv, cp_, half, vb, KfT, NDP);
        }
    }

    __syncthreads();

    // ---- H phase: thread = row pair x 8 columns ----
    {
        const int rp = tid & 7;
        const int cg = tid >> 3;
        const float2* sb = (const float2*)sv + rp;
        const int qb = (cg << 3) - RL;
        if (qb >= 0 && qb + ND + 7 <= 255) {
            float ax[8] = {}, ay[8] = {};
            float2 ring[8];
            const float2* p = sb + qb * (SVSTRIDE / 2);
            #pragma unroll
            for (int m = 0; m < 8; ++m) ring[m] = p[m * (SVSTRIDE / 2)];
            HTap<TI, 0>::run(ax, ay, ring, p);
            store_out(gout, m0, rp, cg, ax, ay);
        } else {
            h_boundary(sb, gout, rp, cg, qb, KfT, NDP, m0);
        }
    }
}

// ---------------------------------------------------------------------------
__global__ void __launch_bounds__(256, 4) blur_fused(
    const float* __restrict__ src, float* __restrict__ dst,
    const int* __restrict__ t, const __grid_constant__ BlurParams P)
{
    __shared__ float sv[IMG * SVSTRIDE];

    const int tid = threadIdx.x;
    const int m0 = blockIdx.x << 4;                 // tile's first output row
    const int bc = blockIdx.z * CHAN + blockIdx.y;
    const float* img = src + ((long)bc << 16);
    float* gout = dst + ((long)bc << 16);

    const int tb = t[blockIdx.z];
    if (tb <= 0) {                                  // identity (safety)
        const float4* s4 = (const float4*)(img + (m0 << 8));
        float4* d4 = (float4*)(gout + (m0 << 8));
        #pragma unroll
        for (int i = 0; i < 4; ++i) d4[tid + 256 * i] = s4[tid + 256 * i];
        return;
    }
    const int ti = (tb > NT) ? (NT - 1) : (tb - 1);

    switch (ti) {
#define CASE_TI(TI) case TI: tile_body<TI>(img, gout, sv, tid, m0, P.K[TI]); break;
        CASE_TI(0)  CASE_TI(1)  CASE_TI(2)  CASE_TI(3)  CASE_TI(4)
        CASE_TI(5)  CASE_TI(6)  CASE_TI(7)  CASE_TI(8)  CASE_TI(9)
        CASE_TI(10) CASE_TI(11) CASE_TI(12) CASE_TI(13) CASE_TI(14)
        CASE_TI(15) CASE_TI(16) CASE_TI(17) CASE_TI(18)
#undef CASE_TI
        default: break;
    }
}

// ---------------------------------------------------------------------------
extern "C" void kernel_launch(void* const* d_in, const int* in_sizes, int n_in,
                              void* d_out, int out_size) {
    const float* x = (const float*)d_in[0];
    const int* t = (const int*)d_in[1];
    float* out = (float*)d_out;

    // Runtime weight copy for boundary paths (zero-padded to 8-multiples).
    static BlurParams P = {};
    for (int ti = 0; ti < NT; ++ti) {
        for (int j = 0; j < KW; ++j)
            P.K[ti][j] = (j < KT.nd[ti]) ? KT.w[ti][j] : 0.0f;
    }

    dim3 block(256);
    dim3 grid(IMG / 16, CHAN, BATCH);   // 16 x 3 x 64 = 3072 CTAs
    blur_fused<<<grid, block>>>(x, out, t, P);
}